// round 16
// baseline (speedup 1.0000x reference)
#include <cuda_runtime.h>
#include <cuda_bf16.h>
#include <cstdint>
#include <cstddef>

#define HW   4096
#define CC   256
#define BB   4
#define NGRP 32
#define CPG  8
#define KSPLIT 768   // 3 * CC logical K for hi/lo split conv1

// ---------------------------------------------------------------------------
// Scratch (static device globals)
// ---------------------------------------------------------------------------
__device__ float g_x1 [(size_t)BB * CC * HW];            // conv1 out [b,c,s] fp32 (residual)
__device__ __nv_bfloat16 g_hb [(size_t)BB * HW * CC];    // groupnorm out [b,s,c]
__device__ __nv_bfloat16 g_qkb[(size_t)BB * HW * 512];   // q|k [b,s,512]
__device__ __nv_bfloat16 g_vb [(size_t)BB * CC * HW];    // v [b,c,t]
__device__ __nv_bfloat16 g_o2b[(size_t)BB * HW * CC];    // attention out [b,s,c]
__device__ __nv_bfloat16 g_xs [(size_t)BB * HW * 512];   // x split [s,512]: [hi,lo]
__device__ __nv_bfloat16 g_ws [CC * KSPLIT];             // dw split [c,768]: [hi,lo,hi]
__device__ __nv_bfloat16 g_wqk[512 * CC];                // wq|wk bf16
__device__ __nv_bfloat16 g_wv[CC * CC], g_wp[CC * CC];
__device__ float g_bqk[512];
__device__ float g_gsum[BB * NGRP];
__device__ float g_gsum2[BB * NGRP];

// ---------------------------------------------------------------------------
// mma.sync helpers
// ---------------------------------------------------------------------------
__device__ __forceinline__ uint32_t smem_u32(const void* p) {
    return (uint32_t)__cvta_generic_to_shared(p);
}
__device__ __forceinline__ void cp16(uint32_t dst, const void* src) {
    asm volatile("cp.async.cg.shared.global [%0], [%1], 16;" :: "r"(dst), "l"(src));
}
#define CP_COMMIT() asm volatile("cp.async.commit_group;" ::: "memory")
#define CP_WAIT(N)  asm volatile("cp.async.wait_group %0;" :: "n"(N) : "memory")

__device__ __forceinline__ void ldm_x4(uint32_t* r, uint32_t addr) {
    asm volatile("ldmatrix.sync.aligned.m8n8.x4.shared.b16 {%0,%1,%2,%3}, [%4];"
        : "=r"(r[0]), "=r"(r[1]), "=r"(r[2]), "=r"(r[3]) : "r"(addr));
}
__device__ __forceinline__ void mma16816(float* d, const uint32_t* a, const uint32_t* b) {
    asm volatile("mma.sync.aligned.m16n8k16.row.col.f32.bf16.bf16.f32 "
        "{%0,%1,%2,%3}, {%4,%5,%6,%7}, {%8,%9}, {%0,%1,%2,%3};"
        : "+f"(d[0]), "+f"(d[1]), "+f"(d[2]), "+f"(d[3])
        : "r"(a[0]), "r"(a[1]), "r"(a[2]), "r"(a[3]), "r"(b[0]), "r"(b[1]));
}
// 128-byte rows, 8 chunks of 16B
__device__ __forceinline__ uint32_t swz64(int row, int ch) {
    return (uint32_t)(row * 128 + ((ch ^ (row & 7)) << 4));
}
// 512-byte rows, 32 chunks of 16B (swizzle within each 128B subgroup)
__device__ __forceinline__ uint32_t swzQ(int row, int ch) {
    return (uint32_t)(row * 512 + (((ch & 0x18) | ((ch & 7) ^ (row & 7))) << 4));
}
// byte-addressed variant of swz64 (4B-aligned stores into 128B rows)
__device__ __forceinline__ uint32_t swz64b(int row, int byte) {
    return (uint32_t)(row * 128 + ((((byte >> 4) ^ (row & 7)) << 4) | (byte & 15)));
}

// ---------------------------------------------------------------------------
// Generic bf16 mma.sync GEMM: 128x128 block, 4 warps (2x2), TK=64, 3-stage.
// BMAP: conv1 B-chunk remap (chunk c -> c<4 ? c : c-4 in a 512-wide buffer).
// GSTAT: accumulate per-(batch,group) sum/sumsq of fp32 outputs (GroupNorm).
// ---------------------------------------------------------------------------
#define TK 64
#define STG_BYTES 32768
#define MMA_SMEM (3 * STG_BYTES)

template<int OUT_BF16, int BIAS, int RES, int BMAP, int GSTAT>
__global__ __launch_bounds__(128, 2)
void mma_gemm(const __nv_bfloat16* __restrict__ A, const __nv_bfloat16* __restrict__ B,
              void* __restrict__ Cp, const float* __restrict__ bias,
              const float* __restrict__ res,
              int K, int lda, int ldb, int ldc,
              long a_bs, long b_bs, long c_bs, float alpha)
{
    extern __shared__ __align__(128) char smem[];
    const uint32_t sb = smem_u32(smem);
    const int tid  = threadIdx.x;
    const int lane = tid & 31;
    const int w    = tid >> 5;
    const int wm   = w & 1;
    const int wn   = w >> 1;
    const int bz   = blockIdx.z;
    const int m0   = blockIdx.y * 128;
    const int n0   = blockIdx.x * 128;

    const __nv_bfloat16* Ab = A + (size_t)bz * a_bs + (size_t)m0 * lda;
    const __nv_bfloat16* Bb = B + (size_t)bz * b_bs + (size_t)n0 * ldb;

    float acc[4][8][4];
#pragma unroll
    for (int mt = 0; mt < 4; mt++)
#pragma unroll
        for (int nt = 0; nt < 8; nt++)
#pragma unroll
            for (int r = 0; r < 4; r++) acc[mt][nt][r] = 0.0f;

    const int NC = K / TK;

#pragma unroll
    for (int s = 0; s < 2; s++) {
        uint32_t ab = sb + s * STG_BYTES, bb = ab + 16384;
        const __nv_bfloat16* As = Ab + s * TK;
        const __nv_bfloat16* Bs = Bb + s * TK;   // s<4: identity under BMAP
#pragma unroll
        for (int i = 0; i < 8; i++) {
            int j = tid + i * 128;
            int row = j >> 3, ch = j & 7;
            cp16(ab + swz64(row, ch), As + (size_t)row * lda + ch * 8);
            cp16(bb + swz64(row, ch), Bs + (size_t)row * ldb + ch * 8);
        }
        CP_COMMIT();
    }

    int stage = 0;
    for (int c = 0; c < NC; c++) {
        CP_WAIT(1);
        __syncthreads();

        const uint32_t abase = sb + stage * STG_BYTES;
        const uint32_t bbase = abase + 16384;
#pragma unroll
        for (int ks = 0; ks < 4; ks++) {
            uint32_t afr[4][4];
#pragma unroll
            for (int mt = 0; mt < 4; mt++) {
                int row = wm * 64 + mt * 16 + (lane & 15);
                int ch  = ks * 2 + (lane >> 4);
                ldm_x4(afr[mt], abase + swz64(row, ch));
            }
            uint32_t bfr[8][2];
#pragma unroll
            for (int nt2 = 0; nt2 < 4; nt2++) {
                int row = wn * 64 + nt2 * 16 + ((lane >> 4) << 3) + (lane & 7);
                int ch  = ks * 2 + ((lane >> 3) & 1);
                ldm_x4(&bfr[nt2 * 2][0], bbase + swz64(row, ch));
            }
#pragma unroll
            for (int mt = 0; mt < 4; mt++)
#pragma unroll
                for (int nt = 0; nt < 8; nt++)
                    mma16816(acc[mt][nt], afr[mt], bfr[nt]);
        }

        if (c + 2 < NC) {
            int cn = c + 2;
            int bk = BMAP ? (cn < 4 ? cn : cn - 4) : cn;
            int s2 = (stage + 2) % 3;
            uint32_t ab = sb + s2 * STG_BYTES, bb = ab + 16384;
            const __nv_bfloat16* An = Ab + (size_t)cn * TK;
            const __nv_bfloat16* Bn = Bb + (size_t)bk * TK;
#pragma unroll
            for (int i = 0; i < 8; i++) {
                int j = tid + i * 128;
                int row = j >> 3, ch = j & 7;
                cp16(ab + swz64(row, ch), An + (size_t)row * lda + ch * 8);
                cp16(bb + swz64(row, ch), Bn + (size_t)row * ldb + ch * 8);
            }
        }
        CP_COMMIT();
        stage = (stage + 1) % 3;
    }

    const int group = lane >> 2, tid4 = lane & 3;
#pragma unroll
    for (int mt = 0; mt < 4; mt++) {
#pragma unroll
        for (int r = 0; r < 2; r++) {
            const int row = m0 + wm * 64 + mt * 16 + group + r * 8;
            float bm = (BIAS == 2) ? bias[row] : 0.0f;
            if (OUT_BF16) {
                __nv_bfloat16* Cb = (__nv_bfloat16*)Cp + (size_t)bz * c_bs + (size_t)row * ldc;
#pragma unroll
                for (int nt = 0; nt < 8; nt++) {
                    int n = n0 + wn * 64 + nt * 8 + tid4 * 2;
                    float f0 = alpha * acc[mt][nt][r * 2 + 0];
                    float f1 = alpha * acc[mt][nt][r * 2 + 1];
                    if (BIAS == 1) { f0 += bias[n]; f1 += bias[n + 1]; }
                    if (BIAS == 2) { f0 += bm; f1 += bm; }
                    *reinterpret_cast<__nv_bfloat162*>(Cb + n) = __floats2bfloat162_rn(f0, f1);
                }
            } else {
                float* Cf = (float*)Cp + (size_t)bz * c_bs + (size_t)row * ldc;
                const float* Rf = RES ? (res + (size_t)bz * c_bs + (size_t)row * ldc) : nullptr;
                float gs = 0.0f, gs2 = 0.0f;
#pragma unroll
                for (int nt = 0; nt < 8; nt++) {
                    int n = n0 + wn * 64 + nt * 8 + tid4 * 2;
                    float f0 = alpha * acc[mt][nt][r * 2 + 0];
                    float f1 = alpha * acc[mt][nt][r * 2 + 1];
                    if (BIAS == 1) { f0 += bias[n]; f1 += bias[n + 1]; }
                    if (BIAS == 2) { f0 += bm; f1 += bm; }
                    if (RES) { f0 += Rf[n]; f1 += Rf[n + 1]; }
                    if (GSTAT) { gs += f0 + f1; gs2 += f0 * f0 + f1 * f1; }
                    *reinterpret_cast<float2*>(Cf + n) = make_float2(f0, f1);
                }
                if (GSTAT) {
                    gs  += __shfl_xor_sync(0xffffffffu, gs, 1);
                    gs  += __shfl_xor_sync(0xffffffffu, gs, 2);
                    gs2 += __shfl_xor_sync(0xffffffffu, gs2, 1);
                    gs2 += __shfl_xor_sync(0xffffffffu, gs2, 2);
                    if (tid4 == 0) {
                        int bg = bz * NGRP + (row >> 3);
                        atomicAdd(&g_gsum[bg], gs);
                        atomicAdd(&g_gsum2[bg], gs2);
                    }
                }
            }
        }
    }
}

// ---------------------------------------------------------------------------
// Fused flash attention (unchanged from R15).
// smem: Q 64KB @0 | K 2x32KB @65536 | V 2x32KB @131072 | P 16KB @196608
// ---------------------------------------------------------------------------
#define KT 64
#define SM_Q 0
#define SM_K 65536
#define SM_V 131072
#define SM_P 196608
#define ATT_SMEM (196608 + 16384)

__global__ __launch_bounds__(256, 1)
void fused_attn_kernel(const __nv_bfloat16* __restrict__ QK,
                       const __nv_bfloat16* __restrict__ V,
                       __nv_bfloat16* __restrict__ O)
{
    extern __shared__ __align__(128) char smem[];
    __shared__ float psum[128][2];
    const uint32_t sb = smem_u32(smem);
    const int tid  = threadIdx.x;
    const int lane = tid & 31;
    const int w    = tid >> 5;
    const int wm   = w & 3;
    const int wn   = w >> 2;
    const int bz   = blockIdx.z;
    const int m0   = blockIdx.y * 128;

    const __nv_bfloat16* Qg = QK + (size_t)bz * HW * 512 + (size_t)m0 * 512;
    const __nv_bfloat16* Kg = QK + (size_t)bz * HW * 512 + 256;
    const __nv_bfloat16* Vg = V + (size_t)bz * CC * HW;

    float acc_o[2][16][4];
#pragma unroll
    for (int mt = 0; mt < 2; mt++)
#pragma unroll
        for (int nt = 0; nt < 16; nt++)
#pragma unroll
            for (int r = 0; r < 4; r++) acc_o[mt][nt][r] = 0.0f;
    float rs[2][2] = {{0.0f, 0.0f}, {0.0f, 0.0f}};

    {
#pragma unroll
        for (int i = 0; i < 16; i++) {
            int j = tid + i * 256;
            int row = j >> 5, ch = j & 31;
            cp16(sb + SM_Q + swzQ(row, ch), Qg + (size_t)row * 512 + ch * 8);
        }
#pragma unroll
        for (int i = 0; i < 8; i++) {
            int j = tid + i * 256;
            int kr = j >> 5, kc = j & 31;
            cp16(sb + SM_K + swzQ(kr, kc), Kg + (size_t)kr * 512 + kc * 8);
            int vr = j >> 3, vc = j & 7;
            cp16(sb + SM_V + swz64(vr, vc), Vg + (size_t)vr * HW + vc * 8);
        }
        CP_COMMIT();
    }

    const int group = lane >> 2, tid4 = lane & 3;
    const int NC = HW / KT;

    for (int c = 0; c < NC; c++) {
        CP_WAIT(0);
        __syncthreads();

        if (c + 1 < NC) {
            const int t1 = (c + 1) * KT;
            uint32_t kb = sb + SM_K + ((c + 1) & 1) * 32768;
            uint32_t vb2 = sb + SM_V + ((c + 1) & 1) * 32768;
#pragma unroll
            for (int i = 0; i < 8; i++) {
                int j = tid + i * 256;
                int kr = j >> 5, kc = j & 31;
                cp16(kb + swzQ(kr, kc), Kg + (size_t)(t1 + kr) * 512 + kc * 8);
                int vr = j >> 3, vc = j & 7;
                cp16(vb2 + swz64(vr, vc), Vg + (size_t)vr * HW + t1 + vc * 8);
            }
            CP_COMMIT();
        }

        const uint32_t kbase = sb + SM_K + (c & 1) * 32768;
        const uint32_t vbase = sb + SM_V + (c & 1) * 32768;

        float acc_s[2][4][4];
#pragma unroll
        for (int mt = 0; mt < 2; mt++)
#pragma unroll
            for (int nt = 0; nt < 4; nt++)
#pragma unroll
                for (int r = 0; r < 4; r++) acc_s[mt][nt][r] = 0.0f;

#pragma unroll
        for (int ks = 0; ks < 16; ks++) {
            uint32_t afr[2][4];
#pragma unroll
            for (int mt = 0; mt < 2; mt++) {
                int row = wm * 32 + mt * 16 + (lane & 15);
                int ch  = ks * 2 + (lane >> 4);
                ldm_x4(afr[mt], sb + SM_Q + swzQ(row, ch));
            }
            uint32_t bfr[4][2];
#pragma unroll
            for (int nt2 = 0; nt2 < 2; nt2++) {
                int row = wn * 32 + nt2 * 16 + ((lane >> 4) << 3) + (lane & 7);
                int ch  = ks * 2 + ((lane >> 3) & 1);
                ldm_x4(&bfr[nt2 * 2][0], kbase + swzQ(row, ch));
            }
#pragma unroll
            for (int mt = 0; mt < 2; mt++)
#pragma unroll
                for (int nt = 0; nt < 4; nt++)
                    mma16816(acc_s[mt][nt], afr[mt], bfr[nt]);
        }

#pragma unroll
        for (int mt = 0; mt < 2; mt++) {
#pragma unroll
            for (int r = 0; r < 2; r++) {
                int row = wm * 32 + mt * 16 + group + r * 8;
#pragma unroll
                for (int nt = 0; nt < 4; nt++) {
                    float f0 = __expf(acc_s[mt][nt][r * 2 + 0] * 0.0625f);
                    float f1 = __expf(acc_s[mt][nt][r * 2 + 1] * 0.0625f);
                    rs[mt][r] += f0 + f1;
                    __nv_bfloat162 b2 = __floats2bfloat162_rn(f0, f1);
                    int byte = (wn * 32 + nt * 8 + tid4 * 2) * 2;
                    asm volatile("st.shared.b32 [%0], %1;"
                        :: "r"(sb + SM_P + swz64b(row, byte)),
                           "r"(*reinterpret_cast<uint32_t*>(&b2)) : "memory");
                }
            }
        }
        __syncthreads();

#pragma unroll
        for (int ks = 0; ks < 4; ks++) {
            uint32_t afr[2][4];
#pragma unroll
            for (int mt = 0; mt < 2; mt++) {
                int row = wm * 32 + mt * 16 + (lane & 15);
                int ch  = ks * 2 + (lane >> 4);
                ldm_x4(afr[mt], sb + SM_P + swz64(row, ch));
            }
            uint32_t bfr[16][2];
#pragma unroll
            for (int nt2 = 0; nt2 < 8; nt2++) {
                int row = wn * 128 + nt2 * 16 + ((lane >> 4) << 3) + (lane & 7);
                int ch  = ks * 2 + ((lane >> 3) & 1);
                ldm_x4(&bfr[nt2 * 2][0], vbase + swz64(row, ch));
            }
#pragma unroll
            for (int mt = 0; mt < 2; mt++)
#pragma unroll
                for (int nt = 0; nt < 16; nt++)
                    mma16816(acc_o[mt][nt], afr[mt], bfr[nt]);
        }
    }

#pragma unroll
    for (int mt = 0; mt < 2; mt++)
#pragma unroll
        for (int r = 0; r < 2; r++) {
            float s = rs[mt][r];
            s += __shfl_xor_sync(0xffffffffu, s, 1);
            s += __shfl_xor_sync(0xffffffffu, s, 2);
            rs[mt][r] = s;
        }
    if (tid4 == 0) {
#pragma unroll
        for (int mt = 0; mt < 2; mt++)
#pragma unroll
            for (int r = 0; r < 2; r++)
                psum[wm * 32 + mt * 16 + group + r * 8][wn] = rs[mt][r];
    }
    __syncthreads();

#pragma unroll
    for (int mt = 0; mt < 2; mt++) {
#pragma unroll
        for (int r = 0; r < 2; r++) {
            const int lrow = wm * 32 + mt * 16 + group + r * 8;
            const float inv = 1.0f / (psum[lrow][0] + psum[lrow][1]);
            __nv_bfloat16* Ob = O + (size_t)bz * HW * CC + (size_t)(m0 + lrow) * CC;
#pragma unroll
            for (int nt = 0; nt < 16; nt++) {
                int n = wn * 128 + nt * 8 + tid4 * 2;
                float f0 = acc_o[mt][nt][r * 2 + 0] * inv;
                float f1 = acc_o[mt][nt][r * 2 + 1] * inv;
                *reinterpret_cast<__nv_bfloat162*>(Ob + n) = __floats2bfloat162_rn(f0, f1);
            }
        }
    }
}

// ---------------------------------------------------------------------------
// x transpose + hi/lo split -> [s, 512] = [hi(256), lo(256)], bf162 stores
// ---------------------------------------------------------------------------
__global__ void xsplit_kernel(const float* __restrict__ x)
{
    __shared__ float tile[32][33];
    const int b = blockIdx.z;
    const int c0 = blockIdx.y * 32;
    const int s0 = blockIdx.x * 32;
    const int tx = threadIdx.x, ty = threadIdx.y;
    const float* src = x + (size_t)b * CC * HW;
#pragma unroll
    for (int i = 0; i < 32; i += 8)
        tile[ty + i][tx] = src[(size_t)(c0 + ty + i) * HW + s0 + tx];
    __syncthreads();
    __nv_bfloat16* dst = g_xs + (size_t)b * HW * 512;
    const int t = ty * 32 + tx;   // 0..255
#pragma unroll
    for (int u = 0; u < 2; u++) {
        int id = t + u * 256;     // 0..511
        int cp = id & 15;         // c-pair
        int s  = id >> 4;         // 0..31
        float v0 = tile[cp * 2][s], v1 = tile[cp * 2 + 1][s];
        __nv_bfloat16 h0 = __float2bfloat16(v0), h1 = __float2bfloat16(v1);
        __nv_bfloat16 l0 = __float2bfloat16(v0 - __bfloat162float(h0));
        __nv_bfloat16 l1 = __float2bfloat16(v1 - __bfloat162float(h1));
        __nv_bfloat16* row = dst + (size_t)(s0 + s) * 512;
        __nv_bfloat162 hp; hp.x = h0; hp.y = h1;
        __nv_bfloat162 lp; lp.x = l0; lp.y = l1;
        *reinterpret_cast<__nv_bfloat162*>(row + c0 + cp * 2) = hp;
        *reinterpret_cast<__nv_bfloat162*>(row + 256 + c0 + cp * 2) = lp;
    }
}

// ---------------------------------------------------------------------------
// Weight prep (also zeroes GN sums)
// ---------------------------------------------------------------------------
__global__ void wprep_kernel(const float* __restrict__ dw,
                             const float* __restrict__ q, const float* __restrict__ k,
                             const float* __restrict__ v, const float* __restrict__ p,
                             const float* __restrict__ q_b, const float* __restrict__ k_b)
{
    int i = blockIdx.x * 256 + threadIdx.x;
    g_wqk[i]         = __float2bfloat16(q[i]);
    g_wqk[65536 + i] = __float2bfloat16(k[i]);
    g_wv[i] = __float2bfloat16(v[i]);
    g_wp[i] = __float2bfloat16(p[i]);
    float wv_ = dw[i];
    __nv_bfloat16 hi = __float2bfloat16(wv_);
    __nv_bfloat16 lo = __float2bfloat16(wv_ - __bfloat162float(hi));
    int r = i >> 8, c = i & 255;
    g_ws[(size_t)r * KSPLIT + c]       = hi;
    g_ws[(size_t)r * KSPLIT + 256 + c] = lo;
    g_ws[(size_t)r * KSPLIT + 512 + c] = hi;
    if (i < 512) g_bqk[i] = (i < 256) ? q_b[i] : k_b[i - 256];
    if (i < BB * NGRP) { g_gsum[i] = 0.0f; g_gsum2[i] = 0.0f; }
}

// ---------------------------------------------------------------------------
// GroupNorm apply + transpose (mean/istd from conv1-epilogue sums)
// ---------------------------------------------------------------------------
__global__ void gn_apply_t_kernel(const float* __restrict__ gamma,
                                  const float* __restrict__ beta)
{
    __shared__ float tile[32][33];
    const int b = blockIdx.z;
    const int c0 = blockIdx.y * 32;
    const int s0 = blockIdx.x * 32;
    const int tx = threadIdx.x, ty = threadIdx.y;
    const float* src = g_x1 + (size_t)b * CC * HW;
    const float inv_n = 1.0f / (float)(CPG * HW);
#pragma unroll
    for (int i = 0; i < 32; i += 8) {
        int c = c0 + ty + i;
        int bg = b * NGRP + (c >> 3);
        float mu = g_gsum[bg] * inv_n;
        float var = g_gsum2[bg] * inv_n - mu * mu;
        float istd = rsqrtf(var + 1e-5f);
        float v = src[(size_t)c * HW + s0 + tx];
        tile[ty + i][tx] = (v - mu) * istd * gamma[c] + beta[c];
    }
    __syncthreads();
    __nv_bfloat16* dst = g_hb + (size_t)b * HW * CC;
#pragma unroll
    for (int i = 0; i < 32; i += 8) {
        int s = s0 + ty + i;
        dst[(size_t)s * CC + c0 + tx] = __float2bfloat16(tile[tx][ty + i]);
    }
}

// ---------------------------------------------------------------------------
// Launcher
// ---------------------------------------------------------------------------
extern "C" void kernel_launch(void* const* d_in, const int* in_sizes, int n_in,
                              void* d_out, int out_size)
{
    const float* x    = (const float*)d_in[0];
    const float* dw_w = (const float*)d_in[1];
    const float* dw_b = (const float*)d_in[2];
    const float* gn_g = (const float*)d_in[3];
    const float* gn_b = (const float*)d_in[4];
    const float* q_w  = (const float*)d_in[5];
    const float* q_b  = (const float*)d_in[6];
    const float* k_w  = (const float*)d_in[7];
    const float* k_b  = (const float*)d_in[8];
    const float* v_w  = (const float*)d_in[9];
    const float* v_b  = (const float*)d_in[10];
    const float* p_w  = (const float*)d_in[11];
    const float* p_b  = (const float*)d_in[12];
    float* out = (float*)d_out;

    float *x1, *bqk;
    __nv_bfloat16 *hb, *qkb, *vb, *o2b, *xs, *ws, *wqk, *wv, *wp;
    cudaGetSymbolAddress((void**)&x1,   g_x1);
    cudaGetSymbolAddress((void**)&bqk,  g_bqk);
    cudaGetSymbolAddress((void**)&hb,   g_hb);
    cudaGetSymbolAddress((void**)&qkb,  g_qkb);
    cudaGetSymbolAddress((void**)&vb,   g_vb);
    cudaGetSymbolAddress((void**)&o2b,  g_o2b);
    cudaGetSymbolAddress((void**)&xs,   g_xs);
    cudaGetSymbolAddress((void**)&ws,   g_ws);
    cudaGetSymbolAddress((void**)&wqk,  g_wqk);
    cudaGetSymbolAddress((void**)&wv,   g_wv);
    cudaGetSymbolAddress((void**)&wp,   g_wp);

    cudaFuncSetAttribute((const void*)mma_gemm<0,2,0,1,1>, cudaFuncAttributeMaxDynamicSharedMemorySize, MMA_SMEM);
    cudaFuncSetAttribute((const void*)mma_gemm<1,1,0,0,0>, cudaFuncAttributeMaxDynamicSharedMemorySize, MMA_SMEM);
    cudaFuncSetAttribute((const void*)mma_gemm<1,2,0,0,0>, cudaFuncAttributeMaxDynamicSharedMemorySize, MMA_SMEM);
    cudaFuncSetAttribute((const void*)mma_gemm<0,2,1,0,0>, cudaFuncAttributeMaxDynamicSharedMemorySize, MMA_SMEM);
    cudaFuncSetAttribute((const void*)fused_attn_kernel, cudaFuncAttributeMaxDynamicSharedMemorySize, ATT_SMEM);

    const long CHW = (long)CC * HW;
    const long QKW = (long)HW * 512;
    dim3 blk(128);

    // 0) prep
    xsplit_kernel<<<dim3(HW / 32, CC / 32, BB), dim3(32, 8)>>>(x);
    wprep_kernel<<<CC * CC / 256, 256>>>(dw_w, q_w, k_w, v_w, p_w, q_b, k_b);

    // 1) conv1 via hi/lo split GEMM (K=768, B chunks remapped into 512-wide xs)
    //    + fused GroupNorm statistics in the epilogue
    mma_gemm<0,2,0,1,1><<<dim3(HW/128, CC/128, BB), blk, MMA_SMEM>>>(
        ws, xs, x1, dw_b, nullptr, KSPLIT, KSPLIT, 512, HW,
        0, (long)HW * 512, CHW, 1.0f);

    // 2) GroupNorm apply -> hb [s,c] bf16
    gn_apply_t_kernel<<<dim3(HW / 32, CC / 32, BB), dim3(32, 8)>>>(gn_g, gn_b);

    // 3) q|k merged: qkb[s,512] = hb . wqk^T + bqk (bias along n)
    mma_gemm<1,1,0,0,0><<<dim3(4, HW/128, BB), blk, MMA_SMEM>>>(
        hb, wqk, qkb, bqk, nullptr, CC, CC, CC, 512, CHW, 0, QKW, 1.0f);

    // 4) v[c,t] (bias along m)
    mma_gemm<1,2,0,0,0><<<dim3(HW/128, CC/128, BB), blk, MMA_SMEM>>>(
        wv, hb, vb, v_b, nullptr, CC, CC, CC, HW, 0, CHW, CHW, 1.0f);

    // 5) fused attention: softmax(Q.K/16) . V -> o2b [s,c]
    fused_attn_kernel<<<dim3(1, HW / 128, BB), dim3(256), ATT_SMEM>>>(qkb, vb, o2b);

    // 6) out = x1 + wp . o2^T + p_b
    mma_gemm<0,2,1,0,0><<<dim3(HW/128, CC/128, BB), blk, MMA_SMEM>>>(
        wp, o2b, out, p_b, x1, CC, CC, CC, HW, 0, CHW, CHW, 1.0f);
}

// round 17
// speedup vs baseline: 1.0115x; 1.0115x over previous
#include <cuda_runtime.h>
#include <cuda_bf16.h>
#include <cstdint>
#include <cstddef>

#define HW   4096
#define CC   256
#define BB   4
#define NGRP 32
#define CPG  8
#define KSPLIT 768   // 3 * CC for hi/lo split conv1

// ---------------------------------------------------------------------------
// Scratch (static device globals)
// ---------------------------------------------------------------------------
__device__ float g_x1 [(size_t)BB * CC * HW];            // conv1 out [b,c,s] fp32 (residual)
__device__ __nv_bfloat16 g_hb [(size_t)BB * HW * CC];    // groupnorm out [b,s,c]
__device__ __nv_bfloat16 g_qkb[(size_t)BB * HW * 512];   // q|k [b,s,512]
__device__ __nv_bfloat16 g_vb [(size_t)BB * CC * HW];    // v [b,c,t]
__device__ __nv_bfloat16 g_o2b[(size_t)BB * HW * CC];    // attention out [b,s,c]
__device__ __nv_bfloat16 g_xs [(size_t)BB * HW * KSPLIT];// x split [s,768]: [hi,hi,lo]
__device__ __nv_bfloat16 g_ws [CC * KSPLIT];             // dw split [c,768]: [hi,lo,hi]
__device__ __nv_bfloat16 g_wqk[512 * CC];                // wq|wk bf16
__device__ __nv_bfloat16 g_wv[CC * CC], g_wp[CC * CC];
__device__ float g_bqk[512];
__device__ float g_gsum[BB * NGRP];
__device__ float g_gsum2[BB * NGRP];

// ---------------------------------------------------------------------------
// mma.sync helpers
// ---------------------------------------------------------------------------
__device__ __forceinline__ uint32_t smem_u32(const void* p) {
    return (uint32_t)__cvta_generic_to_shared(p);
}
__device__ __forceinline__ void cp16(uint32_t dst, const void* src) {
    asm volatile("cp.async.cg.shared.global [%0], [%1], 16;" :: "r"(dst), "l"(src));
}
#define CP_COMMIT() asm volatile("cp.async.commit_group;" ::: "memory")
#define CP_WAIT(N)  asm volatile("cp.async.wait_group %0;" :: "n"(N) : "memory")

__device__ __forceinline__ void ldm_x4(uint32_t* r, uint32_t addr) {
    asm volatile("ldmatrix.sync.aligned.m8n8.x4.shared.b16 {%0,%1,%2,%3}, [%4];"
        : "=r"(r[0]), "=r"(r[1]), "=r"(r[2]), "=r"(r[3]) : "r"(addr));
}
__device__ __forceinline__ void mma16816(float* d, const uint32_t* a, const uint32_t* b) {
    asm volatile("mma.sync.aligned.m16n8k16.row.col.f32.bf16.bf16.f32 "
        "{%0,%1,%2,%3}, {%4,%5,%6,%7}, {%8,%9}, {%0,%1,%2,%3};"
        : "+f"(d[0]), "+f"(d[1]), "+f"(d[2]), "+f"(d[3])
        : "r"(a[0]), "r"(a[1]), "r"(a[2]), "r"(a[3]), "r"(b[0]), "r"(b[1]));
}
// 128-byte rows, 8 chunks of 16B
__device__ __forceinline__ uint32_t swz64(int row, int ch) {
    return (uint32_t)(row * 128 + ((ch ^ (row & 7)) << 4));
}
// 512-byte rows, 32 chunks of 16B (swizzle within each 128B subgroup)
__device__ __forceinline__ uint32_t swzQ(int row, int ch) {
    return (uint32_t)(row * 512 + (((ch & 0x18) | ((ch & 7) ^ (row & 7))) << 4));
}
// byte-addressed variant of swz64 (4B-aligned stores into 128B rows)
__device__ __forceinline__ uint32_t swz64b(int row, int byte) {
    return (uint32_t)(row * 128 + ((((byte >> 4) ^ (row & 7)) << 4) | (byte & 15)));
}

// ---------------------------------------------------------------------------
// Generic bf16 mma.sync GEMM: 128x128 block, 4 warps (2x2), TK=64, 3-stage.
// GSTAT: accumulate per-(batch,group) sum/sumsq of fp32 outputs (GroupNorm).
// ---------------------------------------------------------------------------
#define TK 64
#define STG_BYTES 32768
#define MMA_SMEM (3 * STG_BYTES)

template<int OUT_BF16, int BIAS, int RES, int GSTAT>
__global__ __launch_bounds__(128, 2)
void mma_gemm(const __nv_bfloat16* __restrict__ A, const __nv_bfloat16* __restrict__ B,
              void* __restrict__ Cp, const float* __restrict__ bias,
              const float* __restrict__ res,
              int K, int lda, int ldb, int ldc,
              long a_bs, long b_bs, long c_bs, float alpha)
{
    extern __shared__ __align__(128) char smem[];
    const uint32_t sb = smem_u32(smem);
    const int tid  = threadIdx.x;
    const int lane = tid & 31;
    const int w    = tid >> 5;
    const int wm   = w & 1;
    const int wn   = w >> 1;
    const int bz   = blockIdx.z;
    const int m0   = blockIdx.y * 128;
    const int n0   = blockIdx.x * 128;

    const __nv_bfloat16* Ab = A + (size_t)bz * a_bs + (size_t)m0 * lda;
    const __nv_bfloat16* Bb = B + (size_t)bz * b_bs + (size_t)n0 * ldb;

    float acc[4][8][4];
#pragma unroll
    for (int mt = 0; mt < 4; mt++)
#pragma unroll
        for (int nt = 0; nt < 8; nt++)
#pragma unroll
            for (int r = 0; r < 4; r++) acc[mt][nt][r] = 0.0f;

    const int NC = K / TK;

#pragma unroll
    for (int s = 0; s < 2; s++) {
        uint32_t ab = sb + s * STG_BYTES, bb = ab + 16384;
        const __nv_bfloat16* As = Ab + s * TK;
        const __nv_bfloat16* Bs = Bb + s * TK;
#pragma unroll
        for (int i = 0; i < 8; i++) {
            int j = tid + i * 128;
            int row = j >> 3, ch = j & 7;
            cp16(ab + swz64(row, ch), As + (size_t)row * lda + ch * 8);
            cp16(bb + swz64(row, ch), Bs + (size_t)row * ldb + ch * 8);
        }
        CP_COMMIT();
    }

    int stage = 0;
    for (int c = 0; c < NC; c++) {
        CP_WAIT(1);
        __syncthreads();

        const uint32_t abase = sb + stage * STG_BYTES;
        const uint32_t bbase = abase + 16384;
#pragma unroll
        for (int ks = 0; ks < 4; ks++) {
            uint32_t afr[4][4];
#pragma unroll
            for (int mt = 0; mt < 4; mt++) {
                int row = wm * 64 + mt * 16 + (lane & 15);
                int ch  = ks * 2 + (lane >> 4);
                ldm_x4(afr[mt], abase + swz64(row, ch));
            }
            uint32_t bfr[8][2];
#pragma unroll
            for (int nt2 = 0; nt2 < 4; nt2++) {
                int row = wn * 64 + nt2 * 16 + ((lane >> 4) << 3) + (lane & 7);
                int ch  = ks * 2 + ((lane >> 3) & 1);
                ldm_x4(&bfr[nt2 * 2][0], bbase + swz64(row, ch));
            }
#pragma unroll
            for (int mt = 0; mt < 4; mt++)
#pragma unroll
                for (int nt = 0; nt < 8; nt++)
                    mma16816(acc[mt][nt], afr[mt], bfr[nt]);
        }

        if (c + 2 < NC) {
            int s2 = (stage + 2) % 3;
            uint32_t ab = sb + s2 * STG_BYTES, bb = ab + 16384;
            const __nv_bfloat16* An = Ab + (size_t)(c + 2) * TK;
            const __nv_bfloat16* Bn = Bb + (size_t)(c + 2) * TK;
#pragma unroll
            for (int i = 0; i < 8; i++) {
                int j = tid + i * 128;
                int row = j >> 3, ch = j & 7;
                cp16(ab + swz64(row, ch), An + (size_t)row * lda + ch * 8);
                cp16(bb + swz64(row, ch), Bn + (size_t)row * ldb + ch * 8);
            }
        }
        CP_COMMIT();
        stage = (stage + 1) % 3;
    }

    const int group = lane >> 2, tid4 = lane & 3;
#pragma unroll
    for (int mt = 0; mt < 4; mt++) {
#pragma unroll
        for (int r = 0; r < 2; r++) {
            const int row = m0 + wm * 64 + mt * 16 + group + r * 8;
            float bm = (BIAS == 2) ? bias[row] : 0.0f;
            if (OUT_BF16) {
                __nv_bfloat16* Cb = (__nv_bfloat16*)Cp + (size_t)bz * c_bs + (size_t)row * ldc;
#pragma unroll
                for (int nt = 0; nt < 8; nt++) {
                    int n = n0 + wn * 64 + nt * 8 + tid4 * 2;
                    float f0 = alpha * acc[mt][nt][r * 2 + 0];
                    float f1 = alpha * acc[mt][nt][r * 2 + 1];
                    if (BIAS == 1) { f0 += bias[n]; f1 += bias[n + 1]; }
                    if (BIAS == 2) { f0 += bm; f1 += bm; }
                    *reinterpret_cast<__nv_bfloat162*>(Cb + n) = __floats2bfloat162_rn(f0, f1);
                }
            } else {
                float* Cf = (float*)Cp + (size_t)bz * c_bs + (size_t)row * ldc;
                const float* Rf = RES ? (res + (size_t)bz * c_bs + (size_t)row * ldc) : nullptr;
                float gs = 0.0f, gs2 = 0.0f;
#pragma unroll
                for (int nt = 0; nt < 8; nt++) {
                    int n = n0 + wn * 64 + nt * 8 + tid4 * 2;
                    float f0 = alpha * acc[mt][nt][r * 2 + 0];
                    float f1 = alpha * acc[mt][nt][r * 2 + 1];
                    if (BIAS == 1) { f0 += bias[n]; f1 += bias[n + 1]; }
                    if (BIAS == 2) { f0 += bm; f1 += bm; }
                    if (RES) { f0 += Rf[n]; f1 += Rf[n + 1]; }
                    if (GSTAT) { gs += f0 + f1; gs2 += f0 * f0 + f1 * f1; }
                    *reinterpret_cast<float2*>(Cf + n) = make_float2(f0, f1);
                }
                if (GSTAT) {
                    gs  += __shfl_xor_sync(0xffffffffu, gs, 1);
                    gs  += __shfl_xor_sync(0xffffffffu, gs, 2);
                    gs2 += __shfl_xor_sync(0xffffffffu, gs2, 1);
                    gs2 += __shfl_xor_sync(0xffffffffu, gs2, 2);
                    if (tid4 == 0) {
                        int bg = bz * NGRP + (row >> 3);
                        atomicAdd(&g_gsum[bg], gs);
                        atomicAdd(&g_gsum2[bg], gs2);
                    }
                }
            }
        }
    }
}

// ---------------------------------------------------------------------------
// Fused flash attention (unchanged from R15).
// smem: Q 64KB @0 | K 2x32KB @65536 | V 2x32KB @131072 | P 16KB @196608
// ---------------------------------------------------------------------------
#define KT 64
#define SM_Q 0
#define SM_K 65536
#define SM_V 131072
#define SM_P 196608
#define ATT_SMEM (196608 + 16384)

__global__ __launch_bounds__(256, 1)
void fused_attn_kernel(const __nv_bfloat16* __restrict__ QK,
                       const __nv_bfloat16* __restrict__ V,
                       __nv_bfloat16* __restrict__ O)
{
    extern __shared__ __align__(128) char smem[];
    __shared__ float psum[128][2];
    const uint32_t sb = smem_u32(smem);
    const int tid  = threadIdx.x;
    const int lane = tid & 31;
    const int w    = tid >> 5;
    const int wm   = w & 3;
    const int wn   = w >> 2;
    const int bz   = blockIdx.z;
    const int m0   = blockIdx.y * 128;

    const __nv_bfloat16* Qg = QK + (size_t)bz * HW * 512 + (size_t)m0 * 512;
    const __nv_bfloat16* Kg = QK + (size_t)bz * HW * 512 + 256;
    const __nv_bfloat16* Vg = V + (size_t)bz * CC * HW;

    float acc_o[2][16][4];
#pragma unroll
    for (int mt = 0; mt < 2; mt++)
#pragma unroll
        for (int nt = 0; nt < 16; nt++)
#pragma unroll
            for (int r = 0; r < 4; r++) acc_o[mt][nt][r] = 0.0f;
    float rs[2][2] = {{0.0f, 0.0f}, {0.0f, 0.0f}};

    {
#pragma unroll
        for (int i = 0; i < 16; i++) {
            int j = tid + i * 256;
            int row = j >> 5, ch = j & 31;
            cp16(sb + SM_Q + swzQ(row, ch), Qg + (size_t)row * 512 + ch * 8);
        }
#pragma unroll
        for (int i = 0; i < 8; i++) {
            int j = tid + i * 256;
            int kr = j >> 5, kc = j & 31;
            cp16(sb + SM_K + swzQ(kr, kc), Kg + (size_t)kr * 512 + kc * 8);
            int vr = j >> 3, vc = j & 7;
            cp16(sb + SM_V + swz64(vr, vc), Vg + (size_t)vr * HW + vc * 8);
        }
        CP_COMMIT();
    }

    const int group = lane >> 2, tid4 = lane & 3;
    const int NC = HW / KT;

    for (int c = 0; c < NC; c++) {
        CP_WAIT(0);
        __syncthreads();

        if (c + 1 < NC) {
            const int t1 = (c + 1) * KT;
            uint32_t kb = sb + SM_K + ((c + 1) & 1) * 32768;
            uint32_t vb2 = sb + SM_V + ((c + 1) & 1) * 32768;
#pragma unroll
            for (int i = 0; i < 8; i++) {
                int j = tid + i * 256;
                int kr = j >> 5, kc = j & 31;
                cp16(kb + swzQ(kr, kc), Kg + (size_t)(t1 + kr) * 512 + kc * 8);
                int vr = j >> 3, vc = j & 7;
                cp16(vb2 + swz64(vr, vc), Vg + (size_t)vr * HW + t1 + vc * 8);
            }
            CP_COMMIT();
        }

        const uint32_t kbase = sb + SM_K + (c & 1) * 32768;
        const uint32_t vbase = sb + SM_V + (c & 1) * 32768;

        float acc_s[2][4][4];
#pragma unroll
        for (int mt = 0; mt < 2; mt++)
#pragma unroll
            for (int nt = 0; nt < 4; nt++)
#pragma unroll
                for (int r = 0; r < 4; r++) acc_s[mt][nt][r] = 0.0f;

#pragma unroll
        for (int ks = 0; ks < 16; ks++) {
            uint32_t afr[2][4];
#pragma unroll
            for (int mt = 0; mt < 2; mt++) {
                int row = wm * 32 + mt * 16 + (lane & 15);
                int ch  = ks * 2 + (lane >> 4);
                ldm_x4(afr[mt], sb + SM_Q + swzQ(row, ch));
            }
            uint32_t bfr[4][2];
#pragma unroll
            for (int nt2 = 0; nt2 < 2; nt2++) {
                int row = wn * 32 + nt2 * 16 + ((lane >> 4) << 3) + (lane & 7);
                int ch  = ks * 2 + ((lane >> 3) & 1);
                ldm_x4(&bfr[nt2 * 2][0], kbase + swzQ(row, ch));
            }
#pragma unroll
            for (int mt = 0; mt < 2; mt++)
#pragma unroll
                for (int nt = 0; nt < 4; nt++)
                    mma16816(acc_s[mt][nt], afr[mt], bfr[nt]);
        }

#pragma unroll
        for (int mt = 0; mt < 2; mt++) {
#pragma unroll
            for (int r = 0; r < 2; r++) {
                int row = wm * 32 + mt * 16 + group + r * 8;
#pragma unroll
                for (int nt = 0; nt < 4; nt++) {
                    float f0 = __expf(acc_s[mt][nt][r * 2 + 0] * 0.0625f);
                    float f1 = __expf(acc_s[mt][nt][r * 2 + 1] * 0.0625f);
                    rs[mt][r] += f0 + f1;
                    __nv_bfloat162 b2 = __floats2bfloat162_rn(f0, f1);
                    int byte = (wn * 32 + nt * 8 + tid4 * 2) * 2;
                    asm volatile("st.shared.b32 [%0], %1;"
                        :: "r"(sb + SM_P + swz64b(row, byte)),
                           "r"(*reinterpret_cast<uint32_t*>(&b2)) : "memory");
                }
            }
        }
        __syncthreads();

#pragma unroll
        for (int ks = 0; ks < 4; ks++) {
            uint32_t afr[2][4];
#pragma unroll
            for (int mt = 0; mt < 2; mt++) {
                int row = wm * 32 + mt * 16 + (lane & 15);
                int ch  = ks * 2 + (lane >> 4);
                ldm_x4(afr[mt], sb + SM_P + swz64(row, ch));
            }
            uint32_t bfr[16][2];
#pragma unroll
            for (int nt2 = 0; nt2 < 8; nt2++) {
                int row = wn * 128 + nt2 * 16 + ((lane >> 4) << 3) + (lane & 7);
                int ch  = ks * 2 + ((lane >> 3) & 1);
                ldm_x4(&bfr[nt2 * 2][0], vbase + swz64(row, ch));
            }
#pragma unroll
            for (int mt = 0; mt < 2; mt++)
#pragma unroll
                for (int nt = 0; nt < 16; nt++)
                    mma16816(acc_o[mt][nt], afr[mt], bfr[nt]);
        }
    }

#pragma unroll
    for (int mt = 0; mt < 2; mt++)
#pragma unroll
        for (int r = 0; r < 2; r++) {
            float s = rs[mt][r];
            s += __shfl_xor_sync(0xffffffffu, s, 1);
            s += __shfl_xor_sync(0xffffffffu, s, 2);
            rs[mt][r] = s;
        }
    if (tid4 == 0) {
#pragma unroll
        for (int mt = 0; mt < 2; mt++)
#pragma unroll
            for (int r = 0; r < 2; r++)
                psum[wm * 32 + mt * 16 + group + r * 8][wn] = rs[mt][r];
    }
    __syncthreads();

#pragma unroll
    for (int mt = 0; mt < 2; mt++) {
#pragma unroll
        for (int r = 0; r < 2; r++) {
            const int lrow = wm * 32 + mt * 16 + group + r * 8;
            const float inv = 1.0f / (psum[lrow][0] + psum[lrow][1]);
            __nv_bfloat16* Ob = O + (size_t)bz * HW * CC + (size_t)(m0 + lrow) * CC;
#pragma unroll
            for (int nt = 0; nt < 16; nt++) {
                int n = wn * 128 + nt * 8 + tid4 * 2;
                float f0 = acc_o[mt][nt][r * 2 + 0] * inv;
                float f1 = acc_o[mt][nt][r * 2 + 1] * inv;
                *reinterpret_cast<__nv_bfloat162*>(Ob + n) = __floats2bfloat162_rn(f0, f1);
            }
        }
    }
}

// ---------------------------------------------------------------------------
// x transpose + hi/lo split (R15 version)
// ---------------------------------------------------------------------------
__global__ void xsplit_kernel(const float* __restrict__ x)
{
    __shared__ float tile[32][33];
    const int b = blockIdx.z;
    const int c0 = blockIdx.y * 32;
    const int s0 = blockIdx.x * 32;
    const int tx = threadIdx.x, ty = threadIdx.y;
    const float* src = x + (size_t)b * CC * HW;
#pragma unroll
    for (int i = 0; i < 32; i += 8)
        tile[ty + i][tx] = src[(size_t)(c0 + ty + i) * HW + s0 + tx];
    __syncthreads();
    __nv_bfloat16* dst = g_xs + (size_t)b * HW * KSPLIT;
#pragma unroll
    for (int i = 0; i < 32; i += 8) {
        int s = s0 + ty + i;
        int c = c0 + tx;
        float v = tile[tx][ty + i];
        __nv_bfloat16 hi = __float2bfloat16(v);
        __nv_bfloat16 lo = __float2bfloat16(v - __bfloat162float(hi));
        __nv_bfloat16* row = dst + (size_t)s * KSPLIT;
        row[c]       = hi;
        row[256 + c] = hi;
        row[512 + c] = lo;
    }
}

// ---------------------------------------------------------------------------
// Weight prep (also zeroes GN sums)
// ---------------------------------------------------------------------------
__global__ void wprep_kernel(const float* __restrict__ dw,
                             const float* __restrict__ q, const float* __restrict__ k,
                             const float* __restrict__ v, const float* __restrict__ p,
                             const float* __restrict__ q_b, const float* __restrict__ k_b)
{
    int i = blockIdx.x * 256 + threadIdx.x;
    g_wqk[i]         = __float2bfloat16(q[i]);
    g_wqk[65536 + i] = __float2bfloat16(k[i]);
    g_wv[i] = __float2bfloat16(v[i]);
    g_wp[i] = __float2bfloat16(p[i]);
    float wv_ = dw[i];
    __nv_bfloat16 hi = __float2bfloat16(wv_);
    __nv_bfloat16 lo = __float2bfloat16(wv_ - __bfloat162float(hi));
    int r = i >> 8, c = i & 255;
    g_ws[(size_t)r * KSPLIT + c]       = hi;
    g_ws[(size_t)r * KSPLIT + 256 + c] = lo;
    g_ws[(size_t)r * KSPLIT + 512 + c] = hi;
    if (i < 512) g_bqk[i] = (i < 256) ? q_b[i] : k_b[i - 256];
    if (i < BB * NGRP) { g_gsum[i] = 0.0f; g_gsum2[i] = 0.0f; }
}

// ---------------------------------------------------------------------------
// GroupNorm apply + transpose (mean/istd from conv1-epilogue sums)
// ---------------------------------------------------------------------------
__global__ void gn_apply_t_kernel(const float* __restrict__ gamma,
                                  const float* __restrict__ beta)
{
    __shared__ float tile[32][33];
    const int b = blockIdx.z;
    const int c0 = blockIdx.y * 32;
    const int s0 = blockIdx.x * 32;
    const int tx = threadIdx.x, ty = threadIdx.y;
    const float* src = g_x1 + (size_t)b * CC * HW;
    const float inv_n = 1.0f / (float)(CPG * HW);
#pragma unroll
    for (int i = 0; i < 32; i += 8) {
        int c = c0 + ty + i;
        int bg = b * NGRP + (c >> 3);
        float mu = g_gsum[bg] * inv_n;
        float var = g_gsum2[bg] * inv_n - mu * mu;
        float istd = rsqrtf(var + 1e-5f);
        float v = src[(size_t)c * HW + s0 + tx];
        tile[ty + i][tx] = (v - mu) * istd * gamma[c] + beta[c];
    }
    __syncthreads();
    __nv_bfloat16* dst = g_hb + (size_t)b * HW * CC;
#pragma unroll
    for (int i = 0; i < 32; i += 8) {
        int s = s0 + ty + i;
        dst[(size_t)s * CC + c0 + tx] = __float2bfloat16(tile[tx][ty + i]);
    }
}

// ---------------------------------------------------------------------------
// Launcher
// ---------------------------------------------------------------------------
extern "C" void kernel_launch(void* const* d_in, const int* in_sizes, int n_in,
                              void* d_out, int out_size)
{
    const float* x    = (const float*)d_in[0];
    const float* dw_w = (const float*)d_in[1];
    const float* dw_b = (const float*)d_in[2];
    const float* gn_g = (const float*)d_in[3];
    const float* gn_b = (const float*)d_in[4];
    const float* q_w  = (const float*)d_in[5];
    const float* q_b  = (const float*)d_in[6];
    const float* k_w  = (const float*)d_in[7];
    const float* k_b  = (const float*)d_in[8];
    const float* v_w  = (const float*)d_in[9];
    const float* v_b  = (const float*)d_in[10];
    const float* p_w  = (const float*)d_in[11];
    const float* p_b  = (const float*)d_in[12];
    float* out = (float*)d_out;

    float *x1, *bqk;
    __nv_bfloat16 *hb, *qkb, *vb, *o2b, *xs, *ws, *wqk, *wv, *wp;
    cudaGetSymbolAddress((void**)&x1,   g_x1);
    cudaGetSymbolAddress((void**)&bqk,  g_bqk);
    cudaGetSymbolAddress((void**)&hb,   g_hb);
    cudaGetSymbolAddress((void**)&qkb,  g_qkb);
    cudaGetSymbolAddress((void**)&vb,   g_vb);
    cudaGetSymbolAddress((void**)&o2b,  g_o2b);
    cudaGetSymbolAddress((void**)&xs,   g_xs);
    cudaGetSymbolAddress((void**)&ws,   g_ws);
    cudaGetSymbolAddress((void**)&wqk,  g_wqk);
    cudaGetSymbolAddress((void**)&wv,   g_wv);
    cudaGetSymbolAddress((void**)&wp,   g_wp);

    cudaFuncSetAttribute((const void*)mma_gemm<0,2,0,1>, cudaFuncAttributeMaxDynamicSharedMemorySize, MMA_SMEM);
    cudaFuncSetAttribute((const void*)mma_gemm<1,1,0,0>, cudaFuncAttributeMaxDynamicSharedMemorySize, MMA_SMEM);
    cudaFuncSetAttribute((const void*)mma_gemm<1,2,0,0>, cudaFuncAttributeMaxDynamicSharedMemorySize, MMA_SMEM);
    cudaFuncSetAttribute((const void*)mma_gemm<0,2,1,0>, cudaFuncAttributeMaxDynamicSharedMemorySize, MMA_SMEM);
    cudaFuncSetAttribute((const void*)fused_attn_kernel, cudaFuncAttributeMaxDynamicSharedMemorySize, ATT_SMEM);

    const long CHW = (long)CC * HW;
    const long QKW = (long)HW * 512;
    dim3 blk(128);

    // 0) prep
    xsplit_kernel<<<dim3(HW / 32, CC / 32, BB), dim3(32, 8)>>>(x);
    wprep_kernel<<<CC * CC / 256, 256>>>(dw_w, q_w, k_w, v_w, p_w, q_b, k_b);

    // 1) conv1 via hi/lo split GEMM (K=768) + fused GroupNorm statistics
    mma_gemm<0,2,0,1><<<dim3(HW/128, CC/128, BB), blk, MMA_SMEM>>>(
        ws, xs, x1, dw_b, nullptr, KSPLIT, KSPLIT, KSPLIT, HW,
        0, (long)HW * KSPLIT, CHW, 1.0f);

    // 2) GroupNorm apply -> hb [s,c] bf16
    gn_apply_t_kernel<<<dim3(HW / 32, CC / 32, BB), dim3(32, 8)>>>(gn_g, gn_b);

    // 3) q|k merged: qkb[s,512] = hb . wqk^T + bqk (bias along n)
    mma_gemm<1,1,0,0><<<dim3(4, HW/128, BB), blk, MMA_SMEM>>>(
        hb, wqk, qkb, bqk, nullptr, CC, CC, CC, 512, CHW, 0, QKW, 1.0f);

    // 4) v[c,t] (bias along m)
    mma_gemm<1,2,0,0><<<dim3(HW/128, CC/128, BB), blk, MMA_SMEM>>>(
        wv, hb, vb, v_b, nullptr, CC, CC, CC, HW, 0, CHW, CHW, 1.0f);

    // 5) fused attention: softmax(Q.K/16) . V -> o2b [s,c]
    fused_attn_kernel<<<dim3(1, HW / 128, BB), dim3(256), ATT_SMEM>>>(qkb, vb, o2b);

    // 6) out = x1 + wp . o2^T + p_b
    mma_gemm<0,2,1,0><<<dim3(HW/128, CC/128, BB), blk, MMA_SMEM>>>(
        wp, o2b, out, p_b, x1, CC, CC, CC, HW, 0, CHW, CHW, 1.0f);
}